// round 4
// baseline (speedup 1.0000x reference)
#include <cuda_runtime.h>
#include <cstdint>

#define B_ 8
#define L_ 8192
#define H_ 128
#define N_ 32
#define G_ 256   /* 2H */

typedef unsigned long long ull;

// Scratch (static __device__ arrays: no allocation anywhere)
__device__ float4 g_wk[H_ * N_];                 // {w_re, w_im, k_re, k_im} per (h,n)
__device__ float  g_y[(size_t)B_ * H_ * L_];     // post-GELU activations, (B,H,L)
__device__ ull    g_wt2[H_ * G_];                // out_w transposed + dup'd: [k][g] = {w,w}
__device__ float  g_pooled[B_ * H_];             // sum over l of GLU output

__device__ __forceinline__ ull fma2(ull a, ull b, ull c) {
    ull d; asm("fma.rn.f32x2 %0,%1,%2,%3;" : "=l"(d) : "l"(a), "l"(b), "l"(c)); return d;
}
__device__ __forceinline__ ull mul2(ull a, ull b) {
    ull d; asm("mul.rn.f32x2 %0,%1,%2;" : "=l"(d) : "l"(a), "l"(b)); return d;
}
__device__ __forceinline__ ull add2(ull a, ull b) {
    ull d; asm("add.rn.f32x2 %0,%1,%2;" : "=l"(d) : "l"(a), "l"(b)); return d;
}
__device__ __forceinline__ ull pack2(float x, float y) {
    ull d; asm("mov.b64 %0,{%1,%2};" : "=l"(d) : "f"(x), "f"(y)); return d;
}
__device__ __forceinline__ float2 unpack2(ull a) {
    float2 r; asm("mov.b64 {%0,%1},%2;" : "=f"(r.x), "=f"(r.y) : "l"(a)); return r;
}

// ---------------------------------------------------------------------------
// Setup: discretized SSM params; transpose+duplicate out_w; zero pooled accum.
// Launched with exactly 32768 threads.
// ---------------------------------------------------------------------------
__global__ void setup_kernel(const float* __restrict__ log_dt,
                             const float* __restrict__ log_A_real,
                             const float* __restrict__ A_imag,
                             const float* __restrict__ C_re,
                             const float* __restrict__ C_im,
                             const float* __restrict__ out_w) {
    int i = blockIdx.x * blockDim.x + threadIdx.x;      // 0..32767
    {   // out_w row-major (2H,H): element [g][k] -> g_wt2[k][g] duplicated
        int g = i & 255, k = i >> 8;
        float v = out_w[g * H_ + k];
        g_wt2[k * G_ + g] = pack2(v, v);
    }
    if (i < H_ * N_) {
        int h = i >> 5;
        float dt = expf(log_dt[h]);
        float ar = -expf(log_A_real[i]);
        float ai = A_imag[i];
        float er = expf(dt * ar);
        float si, co;
        sincosf(dt * ai, &si, &co);
        float wr = er * co, wi = er * si;       // w = exp(dt*A)
        float inv = 1.f / (ar * ar + ai * ai);
        float dr = wr - 1.f;
        float qr = (dr * ar + wi * ai) * inv;   // (w-1)/A
        float qi = (wi * ar - dr * ai) * inv;
        float cr = C_re[i], ci = C_im[i];
        float kr = 2.f * (cr * qr - ci * qi);   // 2*C*(w-1)/A
        float ki = 2.f * (cr * qi + ci * qr);
        g_wk[i] = make_float4(wr, wi, kr, ki);
    }
    if (i < B_ * H_) g_pooled[i] = 0.f;
}

// ---------------------------------------------------------------------------
// S4D scan, f32x2-packed: warp = 2 heads (h, h+64) of one batch; lane = half
// (which head) x 2 packed states. u broadcast via dup'd smem + LDS.128 (no
// SHFL in the loop). x prefetched 2 blocks ahead. Per 16 steps: transposed
// n-reduction from smem, D-skip, GELU(tanh via sigmoid/__expf), coalesced STG.
// ---------------------------------------------------------------------------
#define SSTEP(U2, T) {                          \
    ull nre = fma2(nwi2, sim, (U2));            \
    nre = fma2(wr2, sre, nre);                  \
    ull ti_ = mul2(wr2, sim);                   \
    sim = fma2(wi2, sre, ti_);                  \
    sre = nre;                                  \
    ull o_ = mul2(nki2, sim);                   \
    o_ = fma2(kr2, sre, o_);                    \
    rw[(T)] = o_;                               \
}

#define PROCESS(LL, XV) {                                                   \
    float um = fmaf(e1, (XV).y, fmaf(e0, (XV).x, eb));                      \
    su[wid][lane] = pack2(um, um);                                          \
    __syncwarp();                                                           \
    _Pragma("unroll")                                                       \
    for (int j = 0; j < 8; ++j) {                                           \
        ulonglong2 uu = ub[j];                                              \
        SSTEP(uu.x, 2 * j); SSTEP(uu.y, 2 * j + 1);                         \
    }                                                                       \
    __syncwarp();                                                           \
    ull s_ = rb[wid][half][0][tq];                                          \
    _Pragma("unroll")                                                       \
    for (int sid = 1; sid < 16; ++sid) s_ = add2(s_, rb[wid][half][sid][tq]);\
    float2 sf = unpack2(s_);                                                \
    float yv = sf.x + sf.y + Dh * um;                                       \
    float c_ = fmaf(0.044715f, yv * yv, 1.f);                               \
    float q_ = -1.5957691216f * yv * c_;   /* -2*sqrt(2/pi)*yv*(1+..)   */  \
    float gl = __fdividef(yv, 1.f + __expf(q_));  /* yv*sigmoid(2q)     */  \
    yout[(LL) + tq] = gl;                                                   \
}

__global__ void __launch_bounds__(128) scan_kernel(const float* __restrict__ x,
                                                   const float* __restrict__ enc_w,
                                                   const float* __restrict__ enc_b,
                                                   const float* __restrict__ D) {
    __shared__ ull su[4][32];            // dup'd u per (warp, half*16+t)
    __shared__ ull rb[4][2][16][17];     // [warp][half][sid][t], pad 17
    int tid = threadIdx.x;
    int wid = tid >> 5, lane = tid & 31;
    int half = lane >> 4, tq = lane & 15;
    int p = blockIdx.x * 4 + wid;        // 0..511 head-pairs
    int b = p >> 6, h = (p & 63) + (half << 6);

    float4 w0 = g_wk[h * N_ + 2 * tq], w1 = g_wk[h * N_ + 2 * tq + 1];
    ull wr2  = pack2(w0.x, w1.x);
    ull wi2  = pack2(w0.y, w1.y);
    ull nwi2 = pack2(-w0.y, -w1.y);
    ull kr2  = pack2(w0.z, w1.z);
    ull nki2 = pack2(-w0.w, -w1.w);
    float e0 = enc_w[h], e1 = enc_w[H_ + h], eb = enc_b[h], Dh = D[h];
    const float2* xb = reinterpret_cast<const float2*>(x) + (size_t)b * L_;
    float* yout = g_y + ((size_t)b * H_ + h) * L_;
    const ulonglong2* ub = reinterpret_cast<const ulonglong2*>(&su[wid][half << 4]);
    ull* rw = &rb[wid][half][tq][0];

    ull sre = 0ull, sim = 0ull;
    float2 xva = xb[tq], xvb = xb[16 + tq];
    for (int l0 = 0; l0 < L_; l0 += 32) {
        int pn = (l0 + 32 < L_) ? l0 + 32 : 0;       // prefetch 2 sub-blocks ahead
        float2 na = xb[pn + tq];
        float2 nb = xb[pn + 16 + tq];
        PROCESS(l0, xva);
        PROCESS(l0 + 16, xvb);
        xva = na; xvb = nb;
    }
}

// ---------------------------------------------------------------------------
// GLU projection + pool. 1024 one-tile blocks (b, 64-l tile), 2 blocks/SM.
// Thread tile = 8 g-rows x 8 l. A-frags pre-dup'd (g_wt2) -> pure LDG.128;
// y-frags via conflict-free LDS.128 (l-groups 4tx and 32+4tx).
// ---------------------------------------------------------------------------
#define ROW(r, pa) { acc[r][0] = fma2((pa), v0, acc[r][0]); \
                     acc[r][1] = fma2((pa), v1, acc[r][1]); \
                     acc[r][2] = fma2((pa), v2, acc[r][2]); \
                     acc[r][3] = fma2((pa), v3, acc[r][3]); }

__global__ void __launch_bounds__(256, 2) glu_kernel(const float* __restrict__ out_b) {
    __shared__ float ys[H_ * 68];        // y tile [k][64 l], pad 68
    int tid = threadIdx.x;
    int tx = tid & 7;                    // l-group
    int ty = tid >> 3;                   // 0..31 -> g rows 4ty..4ty+3 (+128 gates)
    int t = blockIdx.x;                  // 0..1023 tiles
    int b = t >> 7, l0 = (t & 127) << 6;

    float bA[4], bG[4];
    #pragma unroll
    for (int i = 0; i < 4; i++) { bA[i] = out_b[4 * ty + i]; bG[i] = out_b[H_ + 4 * ty + i]; }

    const float* yb = g_y + (size_t)b * H_ * L_;
    for (int i = tid; i < H_ * 16; i += 256) {
        int hh = i >> 4, lq = i & 15;
        float4 v = *reinterpret_cast<const float4*>(yb + (size_t)hh * L_ + l0 + lq * 4);
        *reinterpret_cast<float4*>(ys + hh * 68 + lq * 4) = v;
    }
    __syncthreads();

    ull acc[8][4];
    #pragma unroll
    for (int r = 0; r < 8; r++) {
        #pragma unroll
        for (int j = 0; j < 4; j++) acc[r][j] = 0ull;
    }

    #pragma unroll 4
    for (int k = 0; k < H_; ++k) {
        const ull* wa = g_wt2 + k * G_ + 4 * ty;
        ulonglong2 A0 = *reinterpret_cast<const ulonglong2*>(wa);
        ulonglong2 A1 = *reinterpret_cast<const ulonglong2*>(wa + 2);
        ulonglong2 G0 = *reinterpret_cast<const ulonglong2*>(wa + H_);
        ulonglong2 G1 = *reinterpret_cast<const ulonglong2*>(wa + H_ + 2);
        const float* yr = ys + k * 68;
        ulonglong2 V0 = *reinterpret_cast<const ulonglong2*>(yr + 4 * tx);       // l: 4tx..+3
        ulonglong2 V1 = *reinterpret_cast<const ulonglong2*>(yr + 32 + 4 * tx);  // l: 32+4tx..+3
        ull v0 = V0.x, v1 = V0.y, v2 = V1.x, v3 = V1.y;
        ROW(0, A0.x) ROW(1, A0.y) ROW(2, A1.x) ROW(3, A1.y)
        ROW(4, G0.x) ROW(5, G0.y) ROW(6, G1.x) ROW(7, G1.y)
    }

    // GLU + partial pool (registers only), then one RED per g-row
    #pragma unroll
    for (int i = 0; i < 4; i++) {
        float s = 0.f;
        #pragma unroll
        for (int j = 0; j < 4; j++) {
            float2 za = unpack2(acc[i][j]);
            float2 zg = unpack2(acc[4 + i][j]);
            float a0 = za.x + bA[i], a1 = za.y + bA[i];
            float g0 = zg.x + bG[i], g1 = zg.y + bG[i];
            s += a0 * __fdividef(1.f, 1.f + __expf(-g0));
            s += a1 * __fdividef(1.f, 1.f + __expf(-g1));
        }
        atomicAdd(&g_pooled[b * H_ + 4 * ty + i], s);
    }
}

// ---------------------------------------------------------------------------
// Decode: out[b] = (pooled_sum[b,:]/L) . dec_w + dec_b
// ---------------------------------------------------------------------------
__global__ void decode_kernel(const float* __restrict__ dec_w,
                              const float* __restrict__ dec_b,
                              float* __restrict__ out) {
    int wid = threadIdx.x >> 5, lane = threadIdx.x & 31;
    int b = wid;                         // 8 warps, one per batch
    float p = 0.f;
    #pragma unroll
    for (int i = 0; i < 4; i++) {
        int h = lane + 32 * i;
        p += g_pooled[b * H_ + h] * dec_w[h];
    }
    p += __shfl_xor_sync(0xffffffffu, p, 16);
    p += __shfl_xor_sync(0xffffffffu, p, 8);
    p += __shfl_xor_sync(0xffffffffu, p, 4);
    p += __shfl_xor_sync(0xffffffffu, p, 2);
    p += __shfl_xor_sync(0xffffffffu, p, 1);
    if (lane == 0) out[b] = p * (1.f / (float)L_) + dec_b[0];
}

// ---------------------------------------------------------------------------
extern "C" void kernel_launch(void* const* d_in, const int* in_sizes, int n_in,
                              void* d_out, int out_size) {
    const float* x      = (const float*)d_in[0];
    const float* enc_w  = (const float*)d_in[1];
    const float* enc_b  = (const float*)d_in[2];
    const float* log_dt = (const float*)d_in[3];
    const float* log_A  = (const float*)d_in[4];
    const float* A_im   = (const float*)d_in[5];
    const float* C_re   = (const float*)d_in[6];
    const float* C_im   = (const float*)d_in[7];
    const float* D      = (const float*)d_in[8];
    const float* out_w  = (const float*)d_in[9];
    const float* out_b  = (const float*)d_in[10];
    const float* dec_w  = (const float*)d_in[11];
    const float* dec_b  = (const float*)d_in[12];
    float* out = (float*)d_out;

    setup_kernel<<<128, 256>>>(log_dt, log_A, A_im, C_re, C_im, out_w);
    scan_kernel<<<128, 128>>>(x, enc_w, enc_b, D);
    glu_kernel<<<1024, 256>>>(out_b);
    decode_kernel<<<1, 256>>>(dec_w, dec_b, out);
}

// round 5
// speedup vs baseline: 1.2978x; 1.2978x over previous
#include <cuda_runtime.h>
#include <cstdint>

#define B_ 8
#define L_ 8192
#define H_ 128
#define N_ 32
#define G_ 256   /* 2H */
#define T_ 1024  /* chunk length */
#define C_ 8     /* chunks */

typedef unsigned long long ull;

// Scratch (static __device__ arrays: no allocation anywhere)
__device__ float4 g_wk[H_ * N_];                 // {w_re, w_im, k_re, k_im} per (h,n)
__device__ float2 g_wT[H_ * N_];                 // w^T per (h,n)
__device__ float  g_y[(size_t)B_ * H_ * L_];     // post-GELU activations, (B,H,L)
__device__ ull    g_wt2[H_ * G_];                // out_w transposed + dup'd: [k][g] = {w,w}
__device__ float  g_pooled[B_ * H_];             // sum over l of GLU output
// chunk finals / carries: packed f32x2 (states 2tq,2tq+1), idx = ((j*8+b)*128+h)*16+tq
__device__ ull    g_fre[C_ * B_ * H_ * 16];
__device__ ull    g_fim[C_ * B_ * H_ * 16];
__device__ ull    g_cre[C_ * B_ * H_ * 16];
__device__ ull    g_cim[C_ * B_ * H_ * 16];

__device__ __forceinline__ ull fma2(ull a, ull b, ull c) {
    ull d; asm("fma.rn.f32x2 %0,%1,%2,%3;" : "=l"(d) : "l"(a), "l"(b), "l"(c)); return d;
}
__device__ __forceinline__ ull mul2(ull a, ull b) {
    ull d; asm("mul.rn.f32x2 %0,%1,%2;" : "=l"(d) : "l"(a), "l"(b)); return d;
}
__device__ __forceinline__ ull add2(ull a, ull b) {
    ull d; asm("add.rn.f32x2 %0,%1,%2;" : "=l"(d) : "l"(a), "l"(b)); return d;
}
__device__ __forceinline__ ull pack2(float x, float y) {
    ull d; asm("mov.b64 %0,{%1,%2};" : "=l"(d) : "f"(x), "f"(y)); return d;
}
__device__ __forceinline__ float2 unpack2(ull a) {
    float2 r; asm("mov.b64 {%0,%1},%2;" : "=f"(r.x), "=f"(r.y) : "l"(a)); return r;
}

// ---------------------------------------------------------------------------
// Setup: SSM params + w^1024; transpose+duplicate out_w; zero pooled accum.
// 32768 threads.
// ---------------------------------------------------------------------------
__global__ void setup_kernel(const float* __restrict__ log_dt,
                             const float* __restrict__ log_A_real,
                             const float* __restrict__ A_imag,
                             const float* __restrict__ C_re,
                             const float* __restrict__ C_im,
                             const float* __restrict__ out_w) {
    int i = blockIdx.x * blockDim.x + threadIdx.x;      // 0..32767
    {   // out_w row-major (2H,H): element [g][k] -> g_wt2[k][g] duplicated
        int g = i & 255, k = i >> 8;
        float v = out_w[g * H_ + k];
        g_wt2[k * G_ + g] = pack2(v, v);
    }
    if (i < H_ * N_) {
        int h = i >> 5;
        float dt = expf(log_dt[h]);
        float ar = -expf(log_A_real[i]);
        float ai = A_imag[i];
        float er = expf(dt * ar);
        float si, co;
        sincosf(dt * ai, &si, &co);
        float wr = er * co, wi = er * si;       // w = exp(dt*A)
        float inv = 1.f / (ar * ar + ai * ai);
        float dr = wr - 1.f;
        float qr = (dr * ar + wi * ai) * inv;   // (w-1)/A
        float qi = (wi * ar - dr * ai) * inv;
        float cr = C_re[i], ci = C_im[i];
        float kr = 2.f * (cr * qr - ci * qi);   // 2*C*(w-1)/A
        float ki = 2.f * (cr * qi + ci * qr);
        g_wk[i] = make_float4(wr, wi, kr, ki);
        // w^1024 by 10 squarings
        float tr = wr, ti = wi;
        #pragma unroll
        for (int s = 0; s < 10; ++s) {
            float nr = tr * tr - ti * ti;
            ti = 2.f * tr * ti;
            tr = nr;
        }
        g_wT[i] = make_float2(tr, ti);
    }
    if (i < B_ * H_) g_pooled[i] = 0.f;
}

// Common per-warp decode: pair p -> (b, h); lane -> (half, tq)
// half selects head h6 vs h6+64; tq selects packed states (2tq, 2tq+1).

#define SSTEP_F(U2) {                           \
    ull nre = fma2(nwi2, sim, (U2));            \
    nre = fma2(wr2, sre, nre);                  \
    ull ti_ = mul2(wr2, sim);                   \
    sim = fma2(wi2, sre, ti_);                  \
    sre = nre;                                  \
}

#define SSTEP(U2, T) {                          \
    SSTEP_F(U2)                                 \
    ull o_ = mul2(nki2, sim);                   \
    o_ = fma2(kr2, sre, o_);                    \
    rw[(T)] = o_;                               \
}

// ---------------------------------------------------------------------------
// Phase 1: per-chunk local final states (chunks 0..6), with decay truncation.
// Grid: 448 blocks x 256 thr; block -> (chunk j = bid>>6, 8 pairs).
// ---------------------------------------------------------------------------
__global__ void __launch_bounds__(256) carry_kernel(const float* __restrict__ x,
                                                    const float* __restrict__ enc_w,
                                                    const float* __restrict__ enc_b) {
    __shared__ ull su[8][32];
    int tid = threadIdx.x;
    int wid = tid >> 5, lane = tid & 31;
    int half = lane >> 4, tq = lane & 15;
    int j = blockIdx.x >> 6;                     // 0..6
    int p = ((blockIdx.x & 63) << 3) | wid;      // 0..511
    int b = p >> 6, h = (p & 63) + (half << 6);

    float4 w0 = g_wk[h * N_ + 2 * tq], w1 = g_wk[h * N_ + 2 * tq + 1];
    ull wr2  = pack2(w0.x, w1.x);
    ull wi2  = pack2(w0.y, w1.y);
    ull nwi2 = pack2(-w0.y, -w1.y);
    float e0 = enc_w[h], e1 = enc_w[H_ + h], eb = enc_b[h];
    const float2* xb = reinterpret_cast<const float2*>(x) + (size_t)b * L_;
    const ulonglong2* ub = reinterpret_cast<const ulonglong2*>(&su[wid][half << 4]);

    // decay truncation: only last d steps matter, |w|_max^d < 1e-8
    float mm = fmaxf(w0.x * w0.x + w0.y * w0.y, w1.x * w1.x + w1.y * w1.y);
    mm = fmaxf(mm, __shfl_xor_sync(0xffffffffu, mm, 16));
    mm = fmaxf(mm, __shfl_xor_sync(0xffffffffu, mm, 8));
    mm = fmaxf(mm, __shfl_xor_sync(0xffffffffu, mm, 4));
    mm = fmaxf(mm, __shfl_xor_sync(0xffffffffu, mm, 2));
    mm = fmaxf(mm, __shfl_xor_sync(0xffffffffu, mm, 1));
    float nl = -0.5f * logf(mm);                 // per-step decay
    int d = T_;
    if (nl > 1e-5f) {
        float df = 18.43f / nl;
        if (df < (float)T_) d = ((int)df + 32) & ~31;
        if (d > T_) d = T_;
    }
    int lend = (j + 1) * T_;
    int lbeg = lend - d;

    ull sre = 0ull, sim = 0ull;
    float2 xva = xb[lbeg + tq], xvb = xb[lbeg + 16 + tq];
    for (int l0 = lbeg; l0 < lend; l0 += 32) {
        int pn = (l0 + 32 < lend) ? l0 + 32 : lbeg;
        float2 na = xb[pn + tq];
        float2 nb = xb[pn + 16 + tq];
        {   // first 16 steps
            float um = fmaf(e1, xva.y, fmaf(e0, xva.x, eb));
            su[wid][lane] = pack2(um, um);
            __syncwarp();
            #pragma unroll
            for (int q = 0; q < 8; ++q) {
                ulonglong2 uu = ub[q];
                SSTEP_F(uu.x) SSTEP_F(uu.y)
            }
            __syncwarp();
        }
        {   // next 16 steps
            float um = fmaf(e1, xvb.y, fmaf(e0, xvb.x, eb));
            su[wid][lane] = pack2(um, um);
            __syncwarp();
            #pragma unroll
            for (int q = 0; q < 8; ++q) {
                ulonglong2 uu = ub[q];
                SSTEP_F(uu.x) SSTEP_F(uu.y)
            }
            __syncwarp();
        }
        xva = na; xvb = nb;
    }
    int idx = (((j << 3) + b) * H_ + h) * 16 + tq;
    g_fre[idx] = sre;
    g_fim[idx] = sim;
}

// ---------------------------------------------------------------------------
// Phase 2: chunk-level carry scan: c_{j+1} = w^T (.) c_j + f_j.  512 warps.
// ---------------------------------------------------------------------------
__global__ void chain_kernel() {
    int tid = threadIdx.x;
    int wid = tid >> 5, lane = tid & 31;
    int half = lane >> 4, tq = lane & 15;
    int p = blockIdx.x * 8 + wid;                // 0..511
    int b = p >> 6, h = (p & 63) + (half << 6);

    float2 t0 = g_wT[h * N_ + 2 * tq], t1 = g_wT[h * N_ + 2 * tq + 1];
    ull wTr2  = pack2(t0.x, t1.x);
    ull wTi2  = pack2(t0.y, t1.y);
    ull nwTi2 = pack2(-t0.y, -t1.y);

    ull cre = 0ull, cim = 0ull;
    #pragma unroll
    for (int j = 0; j < C_; ++j) {
        int idx = (((j << 3) + b) * H_ + h) * 16 + tq;
        g_cre[idx] = cre;
        g_cim[idx] = cim;
        if (j < C_ - 1) {
            ull fre = g_fre[idx], fim = g_fim[idx];
            ull nre = fma2(wTr2, cre, fma2(nwTi2, cim, fre));
            cim = fma2(wTi2, cre, fma2(wTr2, cim, fim));
            cre = nre;
        }
    }
}

// ---------------------------------------------------------------------------
// Phase 3: full scan per chunk from carry, with output (D-skip + GELU).
// Grid: 512 blocks x 256 thr; block -> (chunk j = bid>>6, 8 pairs).
// ---------------------------------------------------------------------------
#define PROCESS(LL, XV) {                                                   \
    float um = fmaf(e1, (XV).y, fmaf(e0, (XV).x, eb));                      \
    su[wid][lane] = pack2(um, um);                                          \
    __syncwarp();                                                           \
    _Pragma("unroll")                                                       \
    for (int q = 0; q < 8; ++q) {                                           \
        ulonglong2 uu = ub[q];                                              \
        SSTEP(uu.x, 2 * q); SSTEP(uu.y, 2 * q + 1);                         \
    }                                                                       \
    __syncwarp();                                                           \
    ull s0 = add2(rb[wid][half][0][tq],  rb[wid][half][1][tq]);             \
    ull s1 = add2(rb[wid][half][2][tq],  rb[wid][half][3][tq]);             \
    ull s2 = add2(rb[wid][half][4][tq],  rb[wid][half][5][tq]);             \
    ull s3 = add2(rb[wid][half][6][tq],  rb[wid][half][7][tq]);             \
    ull s4 = add2(rb[wid][half][8][tq],  rb[wid][half][9][tq]);             \
    ull s5 = add2(rb[wid][half][10][tq], rb[wid][half][11][tq]);            \
    ull s6 = add2(rb[wid][half][12][tq], rb[wid][half][13][tq]);            \
    ull s7 = add2(rb[wid][half][14][tq], rb[wid][half][15][tq]);            \
    s0 = add2(s0, s1); s2 = add2(s2, s3); s4 = add2(s4, s5); s6 = add2(s6, s7);\
    s0 = add2(s0, s2); s4 = add2(s4, s6);                                   \
    s0 = add2(s0, s4);                                                      \
    float2 sf = unpack2(s0);                                                \
    float yv = sf.x + sf.y + Dh * um;                                       \
    float c_ = fmaf(0.044715f, yv * yv, 1.f);                               \
    float q_ = -1.5957691216f * yv * c_;                                    \
    float gl = __fdividef(yv, 1.f + __expf(q_));  /* yv*sigmoid(2q) */      \
    yout[(LL) + tq] = gl;                                                   \
    __syncwarp();                                                           \
}

__global__ void __launch_bounds__(256) scan_kernel(const float* __restrict__ x,
                                                   const float* __restrict__ enc_w,
                                                   const float* __restrict__ enc_b,
                                                   const float* __restrict__ D) {
    __shared__ ull su[8][32];
    __shared__ ull rb[8][2][16][17];
    int tid = threadIdx.x;
    int wid = tid >> 5, lane = tid & 31;
    int half = lane >> 4, tq = lane & 15;
    int j = blockIdx.x >> 6;                     // 0..7
    int p = ((blockIdx.x & 63) << 3) | wid;      // 0..511
    int b = p >> 6, h = (p & 63) + (half << 6);

    float4 w0 = g_wk[h * N_ + 2 * tq], w1 = g_wk[h * N_ + 2 * tq + 1];
    ull wr2  = pack2(w0.x, w1.x);
    ull wi2  = pack2(w0.y, w1.y);
    ull nwi2 = pack2(-w0.y, -w1.y);
    ull kr2  = pack2(w0.z, w1.z);
    ull nki2 = pack2(-w0.w, -w1.w);
    float e0 = enc_w[h], e1 = enc_w[H_ + h], eb = enc_b[h], Dh = D[h];
    const float2* xb = reinterpret_cast<const float2*>(x) + (size_t)b * L_;
    float* yout = g_y + ((size_t)b * H_ + h) * L_;
    const ulonglong2* ub = reinterpret_cast<const ulonglong2*>(&su[wid][half << 4]);
    ull* rw = &rb[wid][half][tq][0];

    int idx = (((j << 3) + b) * H_ + h) * 16 + tq;
    ull sre = g_cre[idx], sim = g_cim[idx];

    int lbeg = j * T_, lend = lbeg + T_;
    float2 xva = xb[lbeg + tq], xvb = xb[lbeg + 16 + tq];
    for (int l0 = lbeg; l0 < lend; l0 += 32) {
        int pn = (l0 + 32 < lend) ? l0 + 32 : lbeg;
        float2 na = xb[pn + tq];
        float2 nb = xb[pn + 16 + tq];
        PROCESS(l0, xva);
        PROCESS(l0 + 16, xvb);
        xva = na; xvb = nb;
    }
}

// ---------------------------------------------------------------------------
// GLU projection + pool (unchanged from R3: 1024 one-tile blocks, f32x2 FMAs).
// ---------------------------------------------------------------------------
#define ROW(r, pa) { acc[r][0] = fma2((pa), v0, acc[r][0]); \
                     acc[r][1] = fma2((pa), v1, acc[r][1]); \
                     acc[r][2] = fma2((pa), v2, acc[r][2]); \
                     acc[r][3] = fma2((pa), v3, acc[r][3]); }

__global__ void __launch_bounds__(256, 2) glu_kernel(const float* __restrict__ out_b) {
    __shared__ float ys[H_ * 68];        // y tile [k][64 l], pad 68
    int tid = threadIdx.x;
    int tx = tid & 7;                    // l-group
    int ty = tid >> 3;                   // 0..31 -> g rows 4ty..4ty+3 (+128 gates)
    int t = blockIdx.x;                  // 0..1023 tiles
    int b = t >> 7, l0 = (t & 127) << 6;

    float bA[4], bG[4];
    #pragma unroll
    for (int i = 0; i < 4; i++) { bA[i] = out_b[4 * ty + i]; bG[i] = out_b[H_ + 4 * ty + i]; }

    const float* yb = g_y + (size_t)b * H_ * L_;
    for (int i = tid; i < H_ * 16; i += 256) {
        int hh = i >> 4, lq = i & 15;
        float4 v = *reinterpret_cast<const float4*>(yb + (size_t)hh * L_ + l0 + lq * 4);
        *reinterpret_cast<float4*>(ys + hh * 68 + lq * 4) = v;
    }
    __syncthreads();

    ull acc[8][4];
    #pragma unroll
    for (int r = 0; r < 8; r++) {
        #pragma unroll
        for (int jj = 0; jj < 4; jj++) acc[r][jj] = 0ull;
    }

    #pragma unroll 4
    for (int k = 0; k < H_; ++k) {
        const ull* wa = g_wt2 + k * G_ + 4 * ty;
        ulonglong2 A0 = *reinterpret_cast<const ulonglong2*>(wa);
        ulonglong2 A1 = *reinterpret_cast<const ulonglong2*>(wa + 2);
        ulonglong2 G0 = *reinterpret_cast<const ulonglong2*>(wa + H_);
        ulonglong2 G1 = *reinterpret_cast<const ulonglong2*>(wa + H_ + 2);
        const float* yr = ys + k * 68;
        ulonglong2 V0 = *reinterpret_cast<const ulonglong2*>(yr + 4 * tx);       // l: 4tx..+3
        ulonglong2 V1 = *reinterpret_cast<const ulonglong2*>(yr + 32 + 4 * tx);  // l: 32+4tx..+3
        ull v0 = V0.x, v1 = V0.y, v2 = V1.x, v3 = V1.y;
        ROW(0, A0.x) ROW(1, A0.y) ROW(2, A1.x) ROW(3, A1.y)
        ROW(4, G0.x) ROW(5, G0.y) ROW(6, G1.x) ROW(7, G1.y)
    }

    #pragma unroll
    for (int i = 0; i < 4; i++) {
        float s = 0.f;
        #pragma unroll
        for (int jj = 0; jj < 4; jj++) {
            float2 za = unpack2(acc[i][jj]);
            float2 zg = unpack2(acc[4 + i][jj]);
            float a0 = za.x + bA[i], a1 = za.y + bA[i];
            float g0 = zg.x + bG[i], g1 = zg.y + bG[i];
            s += a0 * __fdividef(1.f, 1.f + __expf(-g0));
            s += a1 * __fdividef(1.f, 1.f + __expf(-g1));
        }
        atomicAdd(&g_pooled[b * H_ + 4 * ty + i], s);
    }
}

// ---------------------------------------------------------------------------
// Decode: out[b] = (pooled_sum[b,:]/L) . dec_w + dec_b
// ---------------------------------------------------------------------------
__global__ void decode_kernel(const float* __restrict__ dec_w,
                              const float* __restrict__ dec_b,
                              float* __restrict__ out) {
    int wid = threadIdx.x >> 5, lane = threadIdx.x & 31;
    int b = wid;                         // 8 warps, one per batch
    float p = 0.f;
    #pragma unroll
    for (int i = 0; i < 4; i++) {
        int h = lane + 32 * i;
        p += g_pooled[b * H_ + h] * dec_w[h];
    }
    p += __shfl_xor_sync(0xffffffffu, p, 16);
    p += __shfl_xor_sync(0xffffffffu, p, 8);
    p += __shfl_xor_sync(0xffffffffu, p, 4);
    p += __shfl_xor_sync(0xffffffffu, p, 2);
    p += __shfl_xor_sync(0xffffffffu, p, 1);
    if (lane == 0) out[b] = p * (1.f / (float)L_) + dec_b[0];
}

// ---------------------------------------------------------------------------
extern "C" void kernel_launch(void* const* d_in, const int* in_sizes, int n_in,
                              void* d_out, int out_size) {
    const float* x      = (const float*)d_in[0];
    const float* enc_w  = (const float*)d_in[1];
    const float* enc_b  = (const float*)d_in[2];
    const float* log_dt = (const float*)d_in[3];
    const float* log_A  = (const float*)d_in[4];
    const float* A_im   = (const float*)d_in[5];
    const float* C_re   = (const float*)d_in[6];
    const float* C_im   = (const float*)d_in[7];
    const float* D      = (const float*)d_in[8];
    const float* out_w  = (const float*)d_in[9];
    const float* out_b  = (const float*)d_in[10];
    const float* dec_w  = (const float*)d_in[11];
    const float* dec_b  = (const float*)d_in[12];
    float* out = (float*)d_out;

    setup_kernel<<<128, 256>>>(log_dt, log_A, A_im, C_re, C_im, out_w);
    carry_kernel<<<448, 256>>>(x, enc_w, enc_b);       // chunks 0..6 local finals
    chain_kernel<<<64, 256>>>();                       // chunk-carry scan
    scan_kernel<<<512, 256>>>(x, enc_w, enc_b, D);     // full scan from carries
    glu_kernel<<<1024, 256>>>(out_b);
    decode_kernel<<<1, 256>>>(dec_w, dec_b, out);
}